// round 12
// baseline (speedup 1.0000x reference)
#include <cuda_runtime.h>
#include <cuda_fp16.h>
#include <cstdint>

// ============================================================================
// Problem constants
// ============================================================================
#define BATCH 4096
#define HSZ   2048
#define KDIM  4096          // HSZ + INPUT_SIZE
#define NROWS 8192          // 4*HSZ gate-blocked weight rows

// GEMM tiling: CTA 128(M) x 256(N = 4 gates x 64 j), BK=64
// 544 threads: 16 consumer warps (4x4 grid, 32x64 warp tiles) + 1 producer warp
#define TM 128
#define TN 256
#define BK 64
#define KT (KDIM / BK)      // 64 k-iterations
#define STAGES 4
#define STAGE_A (TM * BK * 2)            // 16384
#define STAGE_B (TN * BK * 2)            // 32768
#define STAGE_BYTES (STAGE_A + STAGE_B)  // 49152
#define CTRL_OFF (STAGES * STAGE_BYTES)  // 196608
#define SMEM_BYTES (1024 + CTRL_OFF + 64)

// fp16 staging in TILED+SWIZZLED layout (ready for cp.async.bulk):
//   g_A16t: tile t = mb*64+kt, 128 rows x 64 k, 16KB each
//   g_W16t: tile t = nb*64+kt, 256 nrows x 64 k, 32KB each
__device__ __half g_A16t[(size_t)BATCH * KDIM];   // 32 MB
__device__ __half g_W16t[(size_t)NROWS * KDIM];   // 64 MB

#define SW128(x) ((x) ^ (((x) >> 3) & 0x70))

// ============================================================================
// PTX helpers (base sm_90 features -> valid under compute_100 target)
// ============================================================================
__device__ __forceinline__ uint32_t s2u(const void* p) {
    uint32_t a;
    asm("{ .reg .u64 t; cvta.to.shared.u64 t, %1; cvt.u32.u64 %0, t; }"
        : "=r"(a) : "l"(p));
    return a;
}
#define MBAR_INIT(a, c) \
    asm volatile("mbarrier.init.shared.b64 [%0], %1;" :: "r"(a), "r"(c) : "memory")
#define MBAR_EXPECT_TX(a, b) \
    asm volatile("mbarrier.arrive.expect_tx.shared.b64 _, [%0], %1;" \
                 :: "r"(a), "r"(b) : "memory")
#define MBAR_ARRIVE(a) \
    asm volatile("mbarrier.arrive.shared.b64 _, [%0];" :: "r"(a) : "memory")
#define MBAR_WAIT(addr, ph) do {                                               \
    uint32_t _a = (addr), _p = (ph), _d;                                       \
    asm volatile("{ .reg .pred p; "                                            \
        "mbarrier.try_wait.parity.acquire.cta.shared::cta.b64 p, [%1], %2; "   \
        "selp.b32 %0, 1, 0, p; }" : "=r"(_d) : "r"(_a), "r"(_p) : "memory");   \
    if (!_d) {                                                                 \
        asm volatile("{ .reg .pred P; "                                        \
        "LW_%=: mbarrier.try_wait.parity.acquire.cta.shared::cta.b64 P, [%0], %1, 0x989680; " \
        "@P bra LD_%=; bra LW_%=; LD_%=: }" :: "r"(_a), "r"(_p) : "memory");   \
    } } while (0)

__device__ __forceinline__ void bulk_g2s(uint32_t dst, const void* src,
                                         uint32_t bytes, uint32_t mbar) {
    asm volatile(
        "cp.async.bulk.shared::cta.global.mbarrier::complete_tx::bytes "
        "[%0], [%1], %2, [%3];"
        :: "r"(dst), "l"(src), "r"(bytes), "r"(mbar) : "memory");
}
__device__ __forceinline__ void ldsm4(uint32_t (&r)[4], uint32_t addr) {
    asm volatile("ldmatrix.sync.aligned.m8n8.x4.shared.b16 {%0,%1,%2,%3}, [%4];"
                 : "=r"(r[0]), "=r"(r[1]), "=r"(r[2]), "=r"(r[3]) : "r"(addr));
}
__device__ __forceinline__ void mma16816(float (&c)[4], const uint32_t (&a)[4],
                                         uint32_t b0, uint32_t b1) {
    asm volatile(
        "mma.sync.aligned.m16n8k16.row.col.f32.f16.f16.f32 "
        "{%0,%1,%2,%3}, {%4,%5,%6,%7}, {%8,%9}, {%0,%1,%2,%3};"
        : "+f"(c[0]), "+f"(c[1]), "+f"(c[2]), "+f"(c[3])
        : "r"(a[0]), "r"(a[1]), "r"(a[2]), "r"(a[3]), "r"(b0), "r"(b1));
}

// ============================================================================
// fp32 -> fp16 conversion into tiled+swizzled layout
// ============================================================================
__global__ void __launch_bounds__(256) k_convA(
    const float* __restrict__ h, const float* __restrict__ x)
{
    const uint32_t c = blockIdx.x * 256u + threadIdx.x;   // < 2,097,152
    const uint32_t tile = c >> 10;                         // mb*64 + kt
    const uint32_t wi = c & 1023u;
    const uint32_t r = wi >> 3, kc = wi & 7u;
    const uint32_t mb = tile >> 6, kt = tile & 63u;
    const uint32_t m = mb * 128u + r;
    const uint32_t kg = kt * 64u + kc * 8u;
    const float* src = (kg < 2048u) ? (h + (size_t)m * 2048u + kg)
                                    : (x + (size_t)m * 2048u + (kg - 2048u));
    float4 v0 = *reinterpret_cast<const float4*>(src);
    float4 v1 = *reinterpret_cast<const float4*>(src + 4);
    union { __half2 h2[4]; uint4 u; } pk;
    pk.h2[0] = __floats2half2_rn(v0.x, v0.y);
    pk.h2[1] = __floats2half2_rn(v0.z, v0.w);
    pk.h2[2] = __floats2half2_rn(v1.x, v1.y);
    pk.h2[3] = __floats2half2_rn(v1.z, v1.w);
    char* dst = reinterpret_cast<char*>(g_A16t) + (size_t)tile * 16384u
              + SW128(r * 128u + kc * 16u);
    *reinterpret_cast<uint4*>(dst) = pk.u;
}

__global__ void __launch_bounds__(256) k_convW(
    const float* __restrict__ Wf, const float* __restrict__ Wi,
    const float* __restrict__ Wg, const float* __restrict__ Wo)
{
    const uint32_t c = blockIdx.x * 256u + threadIdx.x;   // < 4,194,304
    const uint32_t tile = c >> 11;                         // nb*64 + kt
    const uint32_t wi = c & 2047u;
    const uint32_t nl = wi >> 3, kc = wi & 7u;
    const uint32_t nb = tile >> 6, kt = tile & 63u;
    const uint32_t gate = nl >> 6, jl = nl & 63u;
    const float* W = (gate == 0 ? Wf : gate == 1 ? Wi : gate == 2 ? Wg : Wo);
    const float* src = W + (size_t)(nb * 64u + jl) * KDIM + kt * 64u + kc * 8u;
    float4 v0 = *reinterpret_cast<const float4*>(src);
    float4 v1 = *reinterpret_cast<const float4*>(src + 4);
    union { __half2 h2[4]; uint4 u; } pk;
    pk.h2[0] = __floats2half2_rn(v0.x, v0.y);
    pk.h2[1] = __floats2half2_rn(v0.z, v0.w);
    pk.h2[2] = __floats2half2_rn(v1.x, v1.y);
    pk.h2[3] = __floats2half2_rn(v1.z, v1.w);
    char* dst = reinterpret_cast<char*>(g_W16t) + (size_t)tile * 32768u
              + SW128(nl * 128u + kc * 16u);
    *reinterpret_cast<uint4*>(dst) = pk.u;
}

// ============================================================================
// Fused LSTM, warp-specialized: 16 consumer warps + 1 producer warp, NO
// block-wide barriers in the main loop.
//   full[p]:  TX mbarrier (count 1), completed by bulk-copy pair fills
//   empty[p]: count-16 mbarrier, one arrive per consumer warp per consume
// grid = 1024 (bx>>5 = m-tile, bx&31 = j-tile), block = 544
// ============================================================================
__global__ void __launch_bounds__(544, 1) k_lstm(
    const float* __restrict__ cIn,
    const float* __restrict__ bf, const float* __restrict__ bi,
    const float* __restrict__ bg, const float* __restrict__ bo,
    float* __restrict__ out)
{
    extern __shared__ char smem[];
    const uint32_t raw  = s2u(smem);
    const uint32_t base = (raw + 1023u) & ~1023u;     // 1KB aligned stages
    const uint32_t ctrl = base + CTRL_OFF;  // full0,full1,empty0,empty1 (8B ea)
    const uint32_t tid  = threadIdx.x;
    const int wid  = tid >> 5;
    const int lane = tid & 31;
    const int mw = wid >> 2;          // 0..3 (consumer M warp: 32 rows)
    const int nw = wid & 3;           // 0..3 (consumer N warp: 64 cols)

    const int mb = blockIdx.x >> 5;
    const int nb = blockIdx.x & 31;
    const int m0 = mb * TM;
    const int j0 = nb * 64;

    const char* gA = reinterpret_cast<const char*>(g_A16t)
                   + (size_t)(mb * 64) * 16384u;       // + kt*16384
    const char* gB = reinterpret_cast<const char*>(g_W16t)
                   + (size_t)(nb * 64) * 32768u;       // + kt*32768

    if (tid == 0) {
        MBAR_INIT(ctrl + 0, 1);    // full0
        MBAR_INIT(ctrl + 8, 1);    // full1
        MBAR_INIT(ctrl + 16, 16);  // empty0
        MBAR_INIT(ctrl + 24, 16);  // empty1
    }
    __syncthreads();

    float acc[2][8][4];
#pragma unroll
    for (int a = 0; a < 2; ++a)
#pragma unroll
        for (int b = 0; b < 8; ++b)
#pragma unroll
            for (int c = 0; c < 4; ++c) acc[a][b][c] = 0.f;

    if (tid == 512) {
        // ---------------- producer (single thread of warp 16) ----------------
        for (int T = 0; T < KT / 2; ++T) {
            const int p = T & 1;
            const int f = T >> 1;                      // fill index for pair p
            if (f > 0) MBAR_WAIT(ctrl + 16 + p * 8, (f - 1) & 1);
            MBAR_EXPECT_TX(ctrl + p * 8, 2u * STAGE_BYTES);
#pragma unroll
            for (int q = 0; q < 2; ++q) {
                const int kt = 2 * T + q;
                const uint32_t sb = base + (p * 2 + q) * STAGE_BYTES;
                bulk_g2s(sb, gA + (size_t)kt * 16384u, STAGE_A, ctrl + p * 8);
                bulk_g2s(sb + STAGE_A, gB + (size_t)kt * 32768u, STAGE_B,
                         ctrl + p * 8);
            }
        }
    } else if (wid < 16) {
        // ---------------- consumers (16 warps) ----------------
        const int ldRow = lane & 15;
        const int ldKB  = (lane >> 4) << 4;

        auto compute_stage = [&](uint32_t sA) {
            const uint32_t sB = sA + STAGE_A;
#pragma unroll
            for (int ks = 0; ks < 4; ++ks) {          // 4 x k16 per BK=64
                const uint32_t kb = ks << 5;
                uint32_t afr[2][4];
#pragma unroll
                for (int mf = 0; mf < 2; ++mf)
                    ldsm4(afr[mf],
                          sA + SW128((uint32_t)((mw * 32 + mf * 16 + ldRow) * 128)
                                     + kb + ldKB));
                uint32_t bfr[4][4];
#pragma unroll
                for (int pr = 0; pr < 4; ++pr)
                    ldsm4(bfr[pr],
                          sB + SW128((uint32_t)((nw * 64 + pr * 16 + ldRow) * 128)
                                     + kb + ldKB));
#pragma unroll
                for (int mf = 0; mf < 2; ++mf)
#pragma unroll
                    for (int nf = 0; nf < 8; ++nf) {
                        const int pr = nf >> 1, sub = nf & 1;
                        mma16816(acc[mf][nf], afr[mf], bfr[pr][sub],
                                 bfr[pr][sub + 2]);
                    }
            }
        };

        for (int T = 0; T < KT / 2; ++T) {
            const int p = T & 1;
            const int f = T >> 1;
            MBAR_WAIT(ctrl + p * 8, f & 1);            // wait pair filled
            compute_stage(base + (p * 2 + 0) * STAGE_BYTES);
            compute_stage(base + (p * 2 + 1) * STAGE_BYTES);
            if (lane == 0) MBAR_ARRIVE(ctrl + 16 + p * 8);   // pair consumed
        }
    }

    // ---------------- epilogue ----------------
    __syncthreads();                                  // all compute done
    float* sg = reinterpret_cast<float*>(smem + (base - raw));   // [128][260]

    if (wid < 16) {
#pragma unroll
        for (int mf = 0; mf < 2; ++mf)
#pragma unroll
            for (int nf = 0; nf < 8; ++nf) {
                const int r0 = mw * 32 + mf * 16 + (lane >> 2);
                const int cc = nw * 64 + nf * 8 + ((lane & 3) << 1);
                *reinterpret_cast<float2*>(sg + r0 * 260 + cc) =
                    make_float2(acc[mf][nf][0], acc[mf][nf][1]);
                *reinterpret_cast<float2*>(sg + (r0 + 8) * 260 + cc) =
                    make_float2(acc[mf][nf][2], acc[mf][nf][3]);
            }
    }
    __syncthreads();

    if (tid < 512) {
#pragma unroll
        for (int e = 0; e < 16; ++e) {
            const int id = (e << 9) + (int)tid;       // 0..8191
            const int m = id >> 6;                    // 0..127
            const int j = id & 63;                    // 0..63
            const float zf = sg[m * 260 +        j] + __ldg(bf + j0 + j);
            const float zi = sg[m * 260 + 64   + j] + __ldg(bi + j0 + j);
            const float zg = sg[m * 260 + 128  + j] + __ldg(bg + j0 + j);
            const float zo = sg[m * 260 + 192  + j] + __ldg(bo + j0 + j);
            const float ft = 1.f / (1.f + __expf(-zf));
            const float it = 1.f / (1.f + __expf(-zi));
            const float gt = 2.f / (1.f + __expf(-2.f * zg)) - 1.f;
            const float ot = 1.f / (1.f + __expf(-zo));
            const size_t go = (size_t)(m0 + m) * HSZ + j0 + j;
            const float cn = ft * __ldg(cIn + go) + it * gt;
            const float hn = ot * (2.f / (1.f + __expf(-2.f * cn)) - 1.f);
            out[go] = hn;
            out[(size_t)BATCH * HSZ + go] = cn;
        }
    }
}

// ============================================================================
// Launch
// ============================================================================
extern "C" void kernel_launch(void* const* d_in, const int* in_sizes, int n_in,
                              void* d_out, int out_size) {
    const float* x  = (const float*)d_in[0];
    const float* h  = (const float*)d_in[1];
    const float* c  = (const float*)d_in[2];
    const float* Wf = (const float*)d_in[3];
    const float* bf = (const float*)d_in[4];
    const float* Wi = (const float*)d_in[5];
    const float* bi = (const float*)d_in[6];
    const float* Wg = (const float*)d_in[7];
    const float* bg = (const float*)d_in[8];
    const float* Wo = (const float*)d_in[9];
    const float* bo = (const float*)d_in[10];
    float* out = (float*)d_out;

    cudaFuncSetAttribute(k_lstm, cudaFuncAttributeMaxDynamicSharedMemorySize,
                         SMEM_BYTES);

    k_convW<<<16384, 256>>>(Wf, Wi, Wg, Wo);
    k_convA<<<8192, 256>>>(h, x);
    k_lstm<<<1024, 544, SMEM_BYTES>>>(c, bf, bi, bg, bo, out);
}

// round 13
// speedup vs baseline: 1.3417x; 1.3417x over previous
#include <cuda_runtime.h>
#include <cuda_fp16.h>
#include <cstdint>

// ============================================================================
// Problem constants
// ============================================================================
#define BATCH 4096
#define HSZ   2048
#define KDIM  4096          // HSZ + INPUT_SIZE
#define NROWS 8192          // 4*HSZ gate-blocked weight rows

// GEMM tiling: CTA 128(M) x 128(N = 4 gates x 32 j), BK=64, 256 threads,
// 3-stage TMA pipeline, 2 CTAs/SM.
#define TM 128
#define TN 128
#define BK 64
#define KT (KDIM / BK)      // 64 k-iterations
#define STAGES 3
#define STAGE_A (TM * BK * 2)            // 16384
#define STAGE_B (TN * BK * 2)            // 16384
#define STAGE_BYTES (STAGE_A + STAGE_B)  // 32768
#define CTRL_OFF (STAGES * STAGE_BYTES)  // 98304
#define SMEM_BYTES (1024 + CTRL_OFF + 64)   // ~99 KB -> 2 CTAs/SM

// fp16 staging in TILED+SWIZZLED layout (ready for cp.async.bulk):
//   g_A16t: tile t = mb*64+kt (mb 0..31), 128 rows x 64 k, 16KB
//   g_W16t: tile t = nb*64+kt (nb 0..63), 128 nrows(4g x 32j) x 64 k, 16KB
__device__ __half g_A16t[(size_t)BATCH * KDIM];   // 32 MB
__device__ __half g_W16t[(size_t)NROWS * KDIM];   // 64 MB

#define SW128(x) ((x) ^ (((x) >> 3) & 0x70))

// ============================================================================
// PTX helpers (base sm_90 features -> valid under compute_100 target)
// ============================================================================
__device__ __forceinline__ uint32_t s2u(const void* p) {
    uint32_t a;
    asm("{ .reg .u64 t; cvta.to.shared.u64 t, %1; cvt.u32.u64 %0, t; }"
        : "=r"(a) : "l"(p));
    return a;
}
#define MBAR_INIT(a, c) \
    asm volatile("mbarrier.init.shared.b64 [%0], %1;" :: "r"(a), "r"(c) : "memory")
#define MBAR_EXPECT_TX(a, b) \
    asm volatile("mbarrier.arrive.expect_tx.shared.b64 _, [%0], %1;" \
                 :: "r"(a), "r"(b) : "memory")
#define MBAR_WAIT(addr, ph) do {                                               \
    uint32_t _a = (addr), _p = (ph), _d;                                       \
    asm volatile("{ .reg .pred p; "                                            \
        "mbarrier.try_wait.parity.acquire.cta.shared::cta.b64 p, [%1], %2; "   \
        "selp.b32 %0, 1, 0, p; }" : "=r"(_d) : "r"(_a), "r"(_p) : "memory");   \
    if (!_d) {                                                                 \
        asm volatile("{ .reg .pred P; "                                        \
        "LW_%=: mbarrier.try_wait.parity.acquire.cta.shared::cta.b64 P, [%0], %1, 0x989680; " \
        "@P bra LD_%=; bra LW_%=; LD_%=: }" :: "r"(_a), "r"(_p) : "memory");   \
    } } while (0)

__device__ __forceinline__ void bulk_g2s(uint32_t dst, const void* src,
                                         uint32_t bytes, uint32_t mbar) {
    asm volatile(
        "cp.async.bulk.shared::cta.global.mbarrier::complete_tx::bytes "
        "[%0], [%1], %2, [%3];"
        :: "r"(dst), "l"(src), "r"(bytes), "r"(mbar) : "memory");
}
__device__ __forceinline__ void ldsm4(uint32_t (&r)[4], uint32_t addr) {
    asm volatile("ldmatrix.sync.aligned.m8n8.x4.shared.b16 {%0,%1,%2,%3}, [%4];"
                 : "=r"(r[0]), "=r"(r[1]), "=r"(r[2]), "=r"(r[3]) : "r"(addr));
}
__device__ __forceinline__ void mma16816(float (&c)[4], const uint32_t (&a)[4],
                                         uint32_t b0, uint32_t b1) {
    asm volatile(
        "mma.sync.aligned.m16n8k16.row.col.f32.f16.f16.f32 "
        "{%0,%1,%2,%3}, {%4,%5,%6,%7}, {%8,%9}, {%0,%1,%2,%3};"
        : "+f"(c[0]), "+f"(c[1]), "+f"(c[2]), "+f"(c[3])
        : "r"(a[0]), "r"(a[1]), "r"(a[2]), "r"(a[3]), "r"(b0), "r"(b1));
}

// ============================================================================
// fp32 -> fp16 conversion into tiled+swizzled layout
// ============================================================================
__global__ void __launch_bounds__(256) k_convA(
    const float* __restrict__ h, const float* __restrict__ x)
{
    const uint32_t c = blockIdx.x * 256u + threadIdx.x;   // < 2,097,152
    const uint32_t tile = c >> 10;                         // mb*64 + kt
    const uint32_t wi = c & 1023u;
    const uint32_t r = wi >> 3, kc = wi & 7u;
    const uint32_t mb = tile >> 6, kt = tile & 63u;
    const uint32_t m = mb * 128u + r;
    const uint32_t kg = kt * 64u + kc * 8u;
    const float* src = (kg < 2048u) ? (h + (size_t)m * 2048u + kg)
                                    : (x + (size_t)m * 2048u + (kg - 2048u));
    float4 v0 = *reinterpret_cast<const float4*>(src);
    float4 v1 = *reinterpret_cast<const float4*>(src + 4);
    union { __half2 h2[4]; uint4 u; } pk;
    pk.h2[0] = __floats2half2_rn(v0.x, v0.y);
    pk.h2[1] = __floats2half2_rn(v0.z, v0.w);
    pk.h2[2] = __floats2half2_rn(v1.x, v1.y);
    pk.h2[3] = __floats2half2_rn(v1.z, v1.w);
    char* dst = reinterpret_cast<char*>(g_A16t) + (size_t)tile * 16384u
              + SW128(r * 128u + kc * 16u);
    *reinterpret_cast<uint4*>(dst) = pk.u;
}

// W tile: nb 0..63, 128 n-rows = gate*32 + jl (jl 0..31)
__global__ void __launch_bounds__(256) k_convW(
    const float* __restrict__ Wf, const float* __restrict__ Wi,
    const float* __restrict__ Wg, const float* __restrict__ Wo)
{
    const uint32_t c = blockIdx.x * 256u + threadIdx.x;   // < 4,194,304
    const uint32_t tile = c >> 10;                         // nb*64 + kt (0..4095)
    const uint32_t wi = c & 1023u;
    const uint32_t nl = wi >> 3, kc = wi & 7u;             // nl 0..127
    const uint32_t nb = tile >> 6, kt = tile & 63u;
    const uint32_t gate = nl >> 5, jl = nl & 31u;
    const float* W = (gate == 0 ? Wf : gate == 1 ? Wi : gate == 2 ? Wg : Wo);
    const float* src = W + (size_t)(nb * 32u + jl) * KDIM + kt * 64u + kc * 8u;
    float4 v0 = *reinterpret_cast<const float4*>(src);
    float4 v1 = *reinterpret_cast<const float4*>(src + 4);
    union { __half2 h2[4]; uint4 u; } pk;
    pk.h2[0] = __floats2half2_rn(v0.x, v0.y);
    pk.h2[1] = __floats2half2_rn(v0.z, v0.w);
    pk.h2[2] = __floats2half2_rn(v1.x, v1.y);
    pk.h2[3] = __floats2half2_rn(v1.z, v1.w);
    char* dst = reinterpret_cast<char*>(g_W16t) + (size_t)tile * 16384u
              + SW128(nl * 128u + kc * 16u);
    *reinterpret_cast<uint4*>(dst) = pk.u;
}

// ============================================================================
// Fused LSTM: 128x128 CTA tile, 8 warps (2x4: 64x32 warp tiles), 256 threads,
// 3-stage TMA pipeline, 2 CTAs/SM for cross-CTA latency hiding.
// grid = 2048 (bx>>6 = m-tile, bx&63 = j-tile)
// ============================================================================
__global__ void __launch_bounds__(256, 2) k_lstm(
    const float* __restrict__ cIn,
    const float* __restrict__ bf, const float* __restrict__ bi,
    const float* __restrict__ bg, const float* __restrict__ bo,
    float* __restrict__ out)
{
    extern __shared__ char smem[];
    const uint32_t raw  = s2u(smem);
    const uint32_t base = (raw + 1023u) & ~1023u;     // 1KB aligned stages
    const uint32_t ctrl = base + CTRL_OFF;            // 3 full-mbarriers
    const uint32_t tid  = threadIdx.x;
    const int wid  = tid >> 5;
    const int lane = tid & 31;
    const int mw = wid >> 2;          // 0..1  (M warp: 64 rows)
    const int nw = wid & 3;           // 0..3  (N warp: 32 cols = 1 gate slice)

    const int mb = blockIdx.x >> 6;
    const int nb = blockIdx.x & 63;
    const int m0 = mb * TM;
    const int j0 = nb * 32;

    const char* gA = reinterpret_cast<const char*>(g_A16t)
                   + (size_t)(mb * 64) * 16384u;       // + kt*16384
    const char* gB = reinterpret_cast<const char*>(g_W16t)
                   + (size_t)(nb * 64) * 16384u;       // + kt*16384

    if (tid == 0) {
#pragma unroll
        for (int s = 0; s < STAGES; ++s) MBAR_INIT(ctrl + s * 8, 1);
    }
    __syncthreads();

    // prologue: fill stages 0,1 (kt 0,1)
    if (tid == 0) {
#pragma unroll
        for (int s = 0; s < STAGES - 1; ++s) {
            const uint32_t sb = base + s * STAGE_BYTES;
            MBAR_EXPECT_TX(ctrl + s * 8, STAGE_BYTES);
            bulk_g2s(sb, gA + (size_t)s * 16384u, STAGE_A, ctrl + s * 8);
            bulk_g2s(sb + STAGE_A, gB + (size_t)s * 16384u, STAGE_B,
                     ctrl + s * 8);
        }
    }

    float acc[4][4][4];
#pragma unroll
    for (int a = 0; a < 4; ++a)
#pragma unroll
        for (int b = 0; b < 4; ++b)
#pragma unroll
            for (int c = 0; c < 4; ++c) acc[a][b][c] = 0.f;

    const int ldRow = lane & 15;
    const int ldKB  = (lane >> 4) << 4;

    // ---------------- main loop ----------------
    int s = 0, ph = 0;                // stage cursor (stage s, parity ph)
    for (int kt = 0; kt < KT; ++kt) {
        MBAR_WAIT(ctrl + s * 8, ph);
        __syncthreads();              // all warps past stage (kt-1): refill safe

        if (tid == 0) {
            const int ns = kt + STAGES - 1;           // kt+2
            if (ns < KT) {
                const int s2 = (s + STAGES - 1) % STAGES;   // == (kt-1)%3 slot
                const uint32_t sb = base + s2 * STAGE_BYTES;
                MBAR_EXPECT_TX(ctrl + s2 * 8, STAGE_BYTES);
                bulk_g2s(sb, gA + (size_t)ns * 16384u, STAGE_A, ctrl + s2 * 8);
                bulk_g2s(sb + STAGE_A, gB + (size_t)ns * 16384u, STAGE_B,
                         ctrl + s2 * 8);
            }
        }

        const uint32_t sA = base + s * STAGE_BYTES;
        const uint32_t sB = sA + STAGE_A;

#pragma unroll
        for (int ks = 0; ks < 4; ++ks) {              // 4 x k16 per BK=64
            const uint32_t kb = ks << 5;
            uint32_t afr[4][4];
#pragma unroll
            for (int mf = 0; mf < 4; ++mf)
                ldsm4(afr[mf], sA + SW128((uint32_t)((mw * 64 + mf * 16 + ldRow) * 128)
                                          + kb + ldKB));
            uint32_t bfr[2][4];
#pragma unroll
            for (int pr = 0; pr < 2; ++pr)
                ldsm4(bfr[pr], sB + SW128((uint32_t)((nw * 32 + pr * 16 + ldRow) * 128)
                                          + kb + ldKB));
#pragma unroll
            for (int mf = 0; mf < 4; ++mf)
#pragma unroll
                for (int nf = 0; nf < 4; ++nf) {
                    const int pr = nf >> 1, sub = nf & 1;
                    mma16816(acc[mf][nf], afr[mf], bfr[pr][sub], bfr[pr][sub + 2]);
                }
        }

        if (++s == STAGES) { s = 0; ph ^= 1; }
    }

    // ---------------- epilogue ----------------
    __syncthreads();                                  // compute done before alias
    float* sg = reinterpret_cast<float*>(smem + (base - raw));   // [128][132]

#pragma unroll
    for (int mf = 0; mf < 4; ++mf)
#pragma unroll
        for (int nf = 0; nf < 4; ++nf) {
            const int r0 = mw * 64 + mf * 16 + (lane >> 2);
            const int cc = nw * 32 + nf * 8 + ((lane & 3) << 1);
            *reinterpret_cast<float2*>(sg + r0 * 132 + cc) =
                make_float2(acc[mf][nf][0], acc[mf][nf][1]);
            *reinterpret_cast<float2*>(sg + (r0 + 8) * 132 + cc) =
                make_float2(acc[mf][nf][2], acc[mf][nf][3]);
        }
    __syncthreads();

#pragma unroll
    for (int e = 0; e < 16; ++e) {
        const int id = (e << 8) + (int)tid;           // 0..4095
        const int m = id >> 5;                        // 0..127
        const int j = id & 31;                        // 0..31
        const float zf = sg[m * 132 +       j] + __ldg(bf + j0 + j);
        const float zi = sg[m * 132 + 32  + j] + __ldg(bi + j0 + j);
        const float zg = sg[m * 132 + 64  + j] + __ldg(bg + j0 + j);
        const float zo = sg[m * 132 + 96  + j] + __ldg(bo + j0 + j);
        const float ft = 1.f / (1.f + __expf(-zf));
        const float it = 1.f / (1.f + __expf(-zi));
        const float gt = 2.f / (1.f + __expf(-2.f * zg)) - 1.f;
        const float ot = 1.f / (1.f + __expf(-zo));
        const size_t go = (size_t)(m0 + m) * HSZ + j0 + j;
        const float cn = ft * __ldg(cIn + go) + it * gt;
        const float hn = ot * (2.f / (1.f + __expf(-2.f * cn)) - 1.f);
        out[go] = hn;
        out[(size_t)BATCH * HSZ + go] = cn;
    }
}

// ============================================================================
// Launch
// ============================================================================
extern "C" void kernel_launch(void* const* d_in, const int* in_sizes, int n_in,
                              void* d_out, int out_size) {
    const float* x  = (const float*)d_in[0];
    const float* h  = (const float*)d_in[1];
    const float* c  = (const float*)d_in[2];
    const float* Wf = (const float*)d_in[3];
    const float* bf = (const float*)d_in[4];
    const float* Wi = (const float*)d_in[5];
    const float* bi = (const float*)d_in[6];
    const float* Wg = (const float*)d_in[7];
    const float* bg = (const float*)d_in[8];
    const float* Wo = (const float*)d_in[9];
    const float* bo = (const float*)d_in[10];
    float* out = (float*)d_out;

    cudaFuncSetAttribute(k_lstm, cudaFuncAttributeMaxDynamicSharedMemorySize,
                         SMEM_BYTES);

    k_convW<<<16384, 256>>>(Wf, Wi, Wg, Wo);
    k_convA<<<8192, 256>>>(h, x);
    k_lstm<<<2048, 256, SMEM_BYTES>>>(c, bf, bi, bg, bo, out);
}

// round 14
// speedup vs baseline: 1.3942x; 1.0391x over previous
#include <cuda_runtime.h>
#include <cuda_fp16.h>
#include <cstdint>

// ============================================================================
// Problem constants
// ============================================================================
#define BATCH 4096
#define HSZ   2048
#define KDIM  4096          // HSZ + INPUT_SIZE
#define NROWS 8192          // 4*HSZ gate-blocked weight rows

// GEMM tiling: CTA 128(M) x 128(N = 4 gates x 32 j), BK=64, 256 threads,
// 3-stage TMA pipeline, 2 CTAs/SM.
#define TM 128
#define TN 128
#define BK 64
#define KT (KDIM / BK)      // 64 k-iterations
#define STAGES 3
#define STAGE_A (TM * BK * 2)            // 16384
#define STAGE_B (TN * BK * 2)            // 16384
#define STAGE_BYTES (STAGE_A + STAGE_B)  // 32768
#define CTRL_OFF (STAGES * STAGE_BYTES)  // 98304
#define SMEM_BYTES (1024 + CTRL_OFF + 64)   // ~99 KB -> 2 CTAs/SM

// fp16 staging in TILED+SWIZZLED layout (ready for cp.async.bulk):
//   g_A16t: tile t = mb*64+kt (mb 0..31), 128 rows x 64 k, 16KB
//   g_W16t: tile t = nb*64+kt (nb 0..63), 128 nrows(4g x 32j) x 64 k, 16KB
__device__ __half g_A16t[(size_t)BATCH * KDIM];   // 32 MB
__device__ __half g_W16t[(size_t)NROWS * KDIM];   // 64 MB

#define SW128(x) ((x) ^ (((x) >> 3) & 0x70))

// ============================================================================
// PTX helpers (base sm_90 features -> valid under compute_100 target)
// ============================================================================
__device__ __forceinline__ uint32_t s2u(const void* p) {
    uint32_t a;
    asm("{ .reg .u64 t; cvta.to.shared.u64 t, %1; cvt.u32.u64 %0, t; }"
        : "=r"(a) : "l"(p));
    return a;
}
#define MBAR_INIT(a, c) \
    asm volatile("mbarrier.init.shared.b64 [%0], %1;" :: "r"(a), "r"(c) : "memory")
#define MBAR_EXPECT_TX(a, b) \
    asm volatile("mbarrier.arrive.expect_tx.shared.b64 _, [%0], %1;" \
                 :: "r"(a), "r"(b) : "memory")
#define MBAR_WAIT(addr, ph) do {                                               \
    uint32_t _a = (addr), _p = (ph), _d;                                       \
    asm volatile("{ .reg .pred p; "                                            \
        "mbarrier.try_wait.parity.acquire.cta.shared::cta.b64 p, [%1], %2; "   \
        "selp.b32 %0, 1, 0, p; }" : "=r"(_d) : "r"(_a), "r"(_p) : "memory");   \
    if (!_d) {                                                                 \
        asm volatile("{ .reg .pred P; "                                        \
        "LW_%=: mbarrier.try_wait.parity.acquire.cta.shared::cta.b64 P, [%0], %1, 0x989680; " \
        "@P bra LD_%=; bra LW_%=; LD_%=: }" :: "r"(_a), "r"(_p) : "memory");   \
    } } while (0)

__device__ __forceinline__ void bulk_g2s(uint32_t dst, const void* src,
                                         uint32_t bytes, uint32_t mbar) {
    asm volatile(
        "cp.async.bulk.shared::cta.global.mbarrier::complete_tx::bytes "
        "[%0], [%1], %2, [%3];"
        :: "r"(dst), "l"(src), "r"(bytes), "r"(mbar) : "memory");
}
__device__ __forceinline__ void ldsm4(uint32_t (&r)[4], uint32_t addr) {
    asm volatile("ldmatrix.sync.aligned.m8n8.x4.shared.b16 {%0,%1,%2,%3}, [%4];"
                 : "=r"(r[0]), "=r"(r[1]), "=r"(r[2]), "=r"(r[3]) : "r"(addr));
}
__device__ __forceinline__ void mma16816(float (&c)[4], const uint32_t (&a)[4],
                                         uint32_t b0, uint32_t b1) {
    asm volatile(
        "mma.sync.aligned.m16n8k16.row.col.f32.f16.f16.f32 "
        "{%0,%1,%2,%3}, {%4,%5,%6,%7}, {%8,%9}, {%0,%1,%2,%3};"
        : "+f"(c[0]), "+f"(c[1]), "+f"(c[2]), "+f"(c[3])
        : "r"(a[0]), "r"(a[1]), "r"(a[2]), "r"(a[3]), "r"(b0), "r"(b1));
}
__device__ __forceinline__ float sigmf(float z) {
    return 1.f / (1.f + __expf(-z));
}
__device__ __forceinline__ float tanhf_(float z) {
    return 2.f / (1.f + __expf(-2.f * z)) - 1.f;
}

// ============================================================================
// Merged fp32 -> fp16 conversion into tiled+swizzled layout.
// Blocks [0, 8192): A chunks. Blocks [8192, 24576): W chunks.
// ============================================================================
__global__ void __launch_bounds__(256) k_conv(
    const float* __restrict__ h, const float* __restrict__ x,
    const float* __restrict__ Wf, const float* __restrict__ Wi,
    const float* __restrict__ Wg, const float* __restrict__ Wo)
{
    if (blockIdx.x < 8192) {
        // ---- A: chunk c -> tile(mb,kt), r(0..127), kc(0..7), 16B each ----
        const uint32_t c = blockIdx.x * 256u + threadIdx.x;   // < 2,097,152
        const uint32_t tile = c >> 10;                         // mb*64 + kt
        const uint32_t wi = c & 1023u;
        const uint32_t r = wi >> 3, kc = wi & 7u;
        const uint32_t mb = tile >> 6, kt = tile & 63u;
        const uint32_t m = mb * 128u + r;
        const uint32_t kg = kt * 64u + kc * 8u;
        const float* src = (kg < 2048u) ? (h + (size_t)m * 2048u + kg)
                                        : (x + (size_t)m * 2048u + (kg - 2048u));
        float4 v0 = *reinterpret_cast<const float4*>(src);
        float4 v1 = *reinterpret_cast<const float4*>(src + 4);
        union { __half2 h2[4]; uint4 u; } pk;
        pk.h2[0] = __floats2half2_rn(v0.x, v0.y);
        pk.h2[1] = __floats2half2_rn(v0.z, v0.w);
        pk.h2[2] = __floats2half2_rn(v1.x, v1.y);
        pk.h2[3] = __floats2half2_rn(v1.z, v1.w);
        char* dst = reinterpret_cast<char*>(g_A16t) + (size_t)tile * 16384u
                  + SW128(r * 128u + kc * 16u);
        *reinterpret_cast<uint4*>(dst) = pk.u;
    } else {
        // ---- W: chunk c -> tile(nb,kt), nl(0..127)=gate*32+jl, kc(0..7) ----
        const uint32_t c = (blockIdx.x - 8192u) * 256u + threadIdx.x; // <4,194,304
        const uint32_t tile = c >> 10;                         // nb*64 + kt
        const uint32_t wi = c & 1023u;
        const uint32_t nl = wi >> 3, kc = wi & 7u;             // nl 0..127
        const uint32_t nb = tile >> 6, kt = tile & 63u;
        const uint32_t gate = nl >> 5, jl = nl & 31u;
        const float* W = (gate == 0 ? Wf : gate == 1 ? Wi : gate == 2 ? Wg : Wo);
        const float* src = W + (size_t)(nb * 32u + jl) * KDIM + kt * 64u + kc * 8u;
        float4 v0 = *reinterpret_cast<const float4*>(src);
        float4 v1 = *reinterpret_cast<const float4*>(src + 4);
        union { __half2 h2[4]; uint4 u; } pk;
        pk.h2[0] = __floats2half2_rn(v0.x, v0.y);
        pk.h2[1] = __floats2half2_rn(v0.z, v0.w);
        pk.h2[2] = __floats2half2_rn(v1.x, v1.y);
        pk.h2[3] = __floats2half2_rn(v1.z, v1.w);
        char* dst = reinterpret_cast<char*>(g_W16t) + (size_t)tile * 16384u
                  + SW128(nl * 128u + kc * 16u);
        *reinterpret_cast<uint4*>(dst) = pk.u;
    }
}

// ============================================================================
// Fused LSTM: 128x128 CTA tile, 8 warps (2 M x 4 N), 256 threads, 3-stage TMA
// pipeline, 2 CTAs/SM.
// Warp N-layout: warp nw covers j-octet [nw*8, nw*8+8) of ALL FOUR gates
// (B rows g*32 + nw*8 + 0..7) -> per-thread acc holds f,i,g,o for its (m,j)
// pairs, enabling a register-only LSTM epilogue (no smem round-trip).
// grid = 2048 (bx>>6 = m-tile, bx&63 = j-tile)
// ============================================================================
__global__ void __launch_bounds__(256, 2) k_lstm(
    const float* __restrict__ cIn,
    const float* __restrict__ bf, const float* __restrict__ bi,
    const float* __restrict__ bg, const float* __restrict__ bo,
    float* __restrict__ out)
{
    extern __shared__ char smem[];
    const uint32_t raw  = s2u(smem);
    const uint32_t base = (raw + 1023u) & ~1023u;     // 1KB aligned stages
    const uint32_t ctrl = base + CTRL_OFF;            // 3 full-mbarriers
    const uint32_t tid  = threadIdx.x;
    const int wid  = tid >> 5;
    const int lane = tid & 31;
    const int mw = wid >> 2;          // 0..1  (M warp: 64 rows)
    const int nw = wid & 3;           // 0..3  (j-octet within each gate)

    const int mb = blockIdx.x >> 6;
    const int nb = blockIdx.x & 63;
    const int m0 = mb * TM;
    const int j0 = nb * 32;

    const char* gA = reinterpret_cast<const char*>(g_A16t)
                   + (size_t)(mb * 64) * 16384u;       // + kt*16384
    const char* gB = reinterpret_cast<const char*>(g_W16t)
                   + (size_t)(nb * 64) * 16384u;       // + kt*16384

    if (tid == 0) {
#pragma unroll
        for (int s = 0; s < STAGES; ++s) MBAR_INIT(ctrl + s * 8, 1);
    }
    __syncthreads();

    // prologue: fill stages 0,1 (kt 0,1)
    if (tid == 0) {
#pragma unroll
        for (int s = 0; s < STAGES - 1; ++s) {
            const uint32_t sb = base + s * STAGE_BYTES;
            MBAR_EXPECT_TX(ctrl + s * 8, STAGE_BYTES);
            bulk_g2s(sb, gA + (size_t)s * 16384u, STAGE_A, ctrl + s * 8);
            bulk_g2s(sb + STAGE_A, gB + (size_t)s * 16384u, STAGE_B,
                     ctrl + s * 8);
        }
    }

    float acc[4][4][4];               // [mf][gate][quad]
#pragma unroll
    for (int a = 0; a < 4; ++a)
#pragma unroll
        for (int b = 0; b < 4; ++b)
#pragma unroll
            for (int c = 0; c < 4; ++c) acc[a][b][c] = 0.f;

    // A ldsm addressing (non-trans, rows 128B apart, K contiguous)
    const int ldRow = lane & 15;
    const int ldKB  = (lane >> 4) << 4;
    // B ldsm addressing: matrix i (lane octet i) = gate i's j-octet nw
    const int bRow = (lane >> 3) * 32 + nw * 8 + (lane & 7);

    // ---------------- main loop ----------------
    int s = 0, ph = 0;                // stage cursor (stage s, parity ph)
    for (int kt = 0; kt < KT; ++kt) {
        MBAR_WAIT(ctrl + s * 8, ph);
        __syncthreads();              // all warps past stage (kt-1): refill safe

        if (tid == 0) {
            const int ns = kt + STAGES - 1;           // kt+2
            if (ns < KT) {
                const int s2 = (s + STAGES - 1) % STAGES;
                const uint32_t sb = base + s2 * STAGE_BYTES;
                MBAR_EXPECT_TX(ctrl + s2 * 8, STAGE_BYTES);
                bulk_g2s(sb, gA + (size_t)ns * 16384u, STAGE_A, ctrl + s2 * 8);
                bulk_g2s(sb + STAGE_A, gB + (size_t)ns * 16384u, STAGE_B,
                         ctrl + s2 * 8);
            }
        }

        const uint32_t sA = base + s * STAGE_BYTES;
        const uint32_t sB = sA + STAGE_A;

#pragma unroll
        for (int ks = 0; ks < 4; ++ks) {              // 4 x k16 per BK=64
            const uint32_t kb = ks << 5;
            uint32_t afr[4][4];
#pragma unroll
            for (int mf = 0; mf < 4; ++mf)
                ldsm4(afr[mf], sA + SW128((uint32_t)((mw * 64 + mf * 16 + ldRow) * 128)
                                          + kb + ldKB));
            uint32_t bk0[4], bk1[4];  // [gate]: k0-7 / k8-15 fragments
            ldsm4(bk0, sB + SW128((uint32_t)(bRow * 128) + kb));
            ldsm4(bk1, sB + SW128((uint32_t)(bRow * 128) + kb + 16));
#pragma unroll
            for (int mf = 0; mf < 4; ++mf)
#pragma unroll
                for (int g = 0; g < 4; ++g)
                    mma16816(acc[mf][g], afr[mf], bk0[g], bk1[g]);
        }

        if (++s == STAGES) { s = 0; ph ^= 1; }
    }

    // ---------------- register-only LSTM epilogue ----------------
    // Thread owns rows mw*64 + mf*16 + {lane>>2, +8}, cols j0 + nw*8 + (lane&3)*2.
    const int jg = j0 + nw * 8 + ((lane & 3) << 1);   // global j (even)
    const float bfv0 = __ldg(bf + jg), bfv1 = __ldg(bf + jg + 1);
    const float biv0 = __ldg(bi + jg), biv1 = __ldg(bi + jg + 1);
    const float bgv0 = __ldg(bg + jg), bgv1 = __ldg(bg + jg + 1);
    const float bov0 = __ldg(bo + jg), bov1 = __ldg(bo + jg + 1);

#pragma unroll
    for (int mf = 0; mf < 4; ++mf) {
#pragma unroll
        for (int rp = 0; rp < 2; ++rp) {
            const int m = m0 + mw * 64 + mf * 16 + rp * 8 + (lane >> 2);
            const size_t go = (size_t)m * HSZ + jg;
            const float2 cv = *reinterpret_cast<const float2*>(cIn + go);
            const int q = rp * 2;
            const float f0 = sigmf(acc[mf][0][q]     + bfv0);
            const float f1 = sigmf(acc[mf][0][q + 1] + bfv1);
            const float i0 = sigmf(acc[mf][1][q]     + biv0);
            const float i1 = sigmf(acc[mf][1][q + 1] + biv1);
            const float g0 = tanhf_(acc[mf][2][q]     + bgv0);
            const float g1 = tanhf_(acc[mf][2][q + 1] + bgv1);
            const float o0 = sigmf(acc[mf][3][q]     + bov0);
            const float o1 = sigmf(acc[mf][3][q + 1] + bov1);
            const float cn0 = f0 * cv.x + i0 * g0;
            const float cn1 = f1 * cv.y + i1 * g1;
            const float hn0 = o0 * tanhf_(cn0);
            const float hn1 = o1 * tanhf_(cn1);
            *reinterpret_cast<float2*>(out + go) = make_float2(hn0, hn1);
            *reinterpret_cast<float2*>(out + (size_t)BATCH * HSZ + go) =
                make_float2(cn0, cn1);
        }
    }
}

// ============================================================================
// Launch
// ============================================================================
extern "C" void kernel_launch(void* const* d_in, const int* in_sizes, int n_in,
                              void* d_out, int out_size) {
    const float* x  = (const float*)d_in[0];
    const float* h  = (const float*)d_in[1];
    const float* c  = (const float*)d_in[2];
    const float* Wf = (const float*)d_in[3];
    const float* bf = (const float*)d_in[4];
    const float* Wi = (const float*)d_in[5];
    const float* bi = (const float*)d_in[6];
    const float* Wg = (const float*)d_in[7];
    const float* bg = (const float*)d_in[8];
    const float* Wo = (const float*)d_in[9];
    const float* bo = (const float*)d_in[10];
    float* out = (float*)d_out;

    cudaFuncSetAttribute(k_lstm, cudaFuncAttributeMaxDynamicSharedMemorySize,
                         SMEM_BYTES);

    k_conv<<<24576, 256>>>(h, x, Wf, Wi, Wg, Wo);
    k_lstm<<<2048, 256, SMEM_BYTES>>>(c, bf, bi, bg, bo, out);
}